// round 2
// baseline (speedup 1.0000x reference)
#include <cuda_runtime.h>
#include <math.h>

#define T_STEPS 160
#define BATCH   640
#define FDIM    40
#define HDIM    768
#define PJDIM   256
#define NLAYERS 3
#define NBLK    120   // <= SM count (148): all blocks co-resident, grid barrier safe

// Persistent recurrent state (scratch) — __device__ globals per harness rules.
__device__ float g_c[NLAYERS][BATCH * HDIM];   // cell states (block-private per tile)
__device__ float g_m[BATCH * HDIM];            // pre-projection output m
__device__ float g_h[NLAYERS][BATCH * PJDIM];  // projected states
__device__ unsigned g_bar_count;               // barrier arrive counter (self-resetting)
__device__ unsigned g_bar_gen;                 // barrier generation (monotonic)

__device__ __forceinline__ float sigf(float x) {
    return 1.0f / (1.0f + __expf(-x));
}

// Software grid barrier. All NBLK blocks are resident (grid <= SM count).
__device__ __forceinline__ void grid_barrier() {
    __syncthreads();
    if (threadIdx.x == 0) {
        __threadfence();
        unsigned gen = *(volatile unsigned*)&g_bar_gen;
        if (atomicAdd(&g_bar_count, 1u) == NBLK - 1) {
            g_bar_count = 0;          // plain store; made visible by fence below
            __threadfence();
            atomicAdd(&g_bar_gen, 1u);
        } else {
            while (*(volatile unsigned*)&g_bar_gen == gen) { __nanosleep(64); }
        }
        __threadfence();
    }
    __syncthreads();
}

// ---------------- gates GEMM + LSTM cell update (device function) -------------
// z = [xpart | h_prev] @ W + b, gate order i,j,f,o at cols n, n+H, n+2H, n+3H.
// c_new = sig(zf+1)*c + sig(zi)*tanh(zj);  m = sig(zo)*tanh(c_new)
// Tile: 64 rows x 64 gate-cols (x4 gates). Exactly 120 tiles = 120 blocks.
template <int XK, bool XCONST>
__device__ void gates_tile(const float* __restrict__ xpart,
                           const float* __restrict__ hprev,
                           const float* __restrict__ W,
                           const float* __restrict__ bias,
                           float* __restrict__ c,
                           float (&sA)[16][64],
                           float (&sW)[16][256])
{
    constexpr int K   = XK + PJDIM;
    constexpr int KUP = ((K + 15) / 16) * 16;

    const int tid = threadIdx.x;
    const int bid = blockIdx.x;
    const int ty  = tid >> 5;   // 0..7 row group
    const int tx  = tid & 31;   // 0..31 col group
    const int m0  = (bid % 10) * 64;
    const int n0  = (bid / 10) * 64;

    float acc[4][8][2];
#pragma unroll
    for (int g = 0; g < 4; g++)
#pragma unroll
        for (int i = 0; i < 8; i++) { acc[g][i][0] = 0.f; acc[g][i][1] = 0.f; }

    const int wcol = n0 + (tid >> 6) * HDIM + (tid & 63);

    for (int k0 = 0; k0 < KUP; k0 += 16) {
        // A tile: 64 rows x 16 k (handles [x|h] concat + K tail)
#pragma unroll
        for (int e = 0; e < 4; e++) {
            int idx = tid * 4 + e;
            int r   = idx >> 4;
            int kk  = idx & 15;
            int kg  = k0 + kk;
            float v;
            if (kg < XK) {
                v = XCONST ? __ldg(&xpart[(m0 + r) * XK + kg])
                           : __ldcg(&xpart[(m0 + r) * XK + kg]);
            } else if (kg < K) {
                v = __ldcg(&hprev[(m0 + r) * PJDIM + (kg - XK)]);
            } else {
                v = 0.0f;
            }
            sA[kk][r] = v;
        }
        // W tile: 16 k x 256 (4 gates x 64 cols)
#pragma unroll
        for (int kk = 0; kk < 16; kk++) {
            int kg = k0 + kk;
            sW[kk][tid] = (kg < K) ? __ldg(&W[kg * (4 * HDIM) + wcol]) : 0.0f;
        }
        __syncthreads();

#pragma unroll
        for (int kk = 0; kk < 16; kk++) {
            float a[8];
#pragma unroll
            for (int i = 0; i < 8; i++) a[i] = sA[kk][ty * 8 + i];
#pragma unroll
            for (int g = 0; g < 4; g++) {
                float2 w = *(const float2*)&sW[kk][g * 64 + tx * 2];
#pragma unroll
                for (int i = 0; i < 8; i++) {
                    acc[g][i][0] = fmaf(a[i], w.x, acc[g][i][0]);
                    acc[g][i][1] = fmaf(a[i], w.y, acc[g][i][1]);
                }
            }
        }
        __syncthreads();
    }

    // Epilogue: cell update. c rows/cols of this tile are block-private across steps.
#pragma unroll
    for (int j = 0; j < 2; j++) {
        int n = n0 + tx * 2 + j;
        float bi = __ldg(&bias[n]);
        float bj = __ldg(&bias[n + HDIM]);
        float bf = __ldg(&bias[n + 2 * HDIM]);
        float bo = __ldg(&bias[n + 3 * HDIM]);
#pragma unroll
        for (int i = 0; i < 8; i++) {
            int row = m0 + ty * 8 + i;
            float zi = acc[0][i][j] + bi;
            float zj = acc[1][i][j] + bj;
            float zf = acc[2][i][j] + bf;
            float zo = acc[3][i][j] + bo;
            float cold = c[row * HDIM + n];
            float cn = sigf(zf + 1.0f) * cold + sigf(zi) * tanhf(zj);
            float mm = sigf(zo) * tanhf(cn);
            c[row * HDIM + n] = cn;
            g_m[row * HDIM + n] = mm;
        }
    }
}

// ---------------- projection GEMM: h = m @ P  (640 x 256 x 768) ---------------
// Tile 64 rows x 32 cols -> 10 x 8 = 80 tiles on blocks 0..79.
__device__ void proj_tile(const float* __restrict__ P,
                          float* __restrict__ h,
                          float (&sA)[16][64],
                          float (&sW)[16][256])
{
    const int tid = threadIdx.x;
    const int bid = blockIdx.x;
    if (bid >= 80) return;

    const int ty = tid >> 4;    // 0..15, 4 rows each
    const int tx = tid & 15;    // 0..15, 2 cols each
    const int m0 = (bid % 10) * 64;
    const int n0 = (bid / 10) * 32;

    float acc[4][2];
#pragma unroll
    for (int i = 0; i < 4; i++) { acc[i][0] = 0.f; acc[i][1] = 0.f; }

    for (int k0 = 0; k0 < HDIM; k0 += 16) {
#pragma unroll
        for (int e = 0; e < 4; e++) {
            int idx = tid * 4 + e;
            int r   = idx >> 4;
            int kk  = idx & 15;
            sA[kk][r] = __ldcg(&g_m[(m0 + r) * HDIM + k0 + kk]);
        }
#pragma unroll
        for (int e = 0; e < 2; e++) {
            int idx = tid + e * 256;
            int kk  = idx >> 5;
            int cc  = idx & 31;
            sW[kk][cc] = __ldg(&P[(k0 + kk) * PJDIM + n0 + cc]);
        }
        __syncthreads();

#pragma unroll
        for (int kk = 0; kk < 16; kk++) {
            float a[4];
#pragma unroll
            for (int i = 0; i < 4; i++) a[i] = sA[kk][ty * 4 + i];
            float2 w = *(const float2*)&sW[kk][tx * 2];
#pragma unroll
            for (int i = 0; i < 4; i++) {
                acc[i][0] = fmaf(a[i], w.x, acc[i][0]);
                acc[i][1] = fmaf(a[i], w.y, acc[i][1]);
            }
        }
        __syncthreads();
    }

#pragma unroll
    for (int i = 0; i < 4; i++) {
        int row = m0 + ty * 4 + i;
        h[row * PJDIM + n0 + tx * 2]     = acc[i][0];
        h[row * PJDIM + n0 + tx * 2 + 1] = acc[i][1];
    }
}

// ---------------- persistent driver kernel (single graph node) ----------------
__global__ void __launch_bounds__(256)
lstm_persistent(const float* __restrict__ x,
                const float* __restrict__ W0, const float* __restrict__ b0,
                const float* __restrict__ P0,
                const float* __restrict__ W1, const float* __restrict__ b1,
                const float* __restrict__ P1,
                const float* __restrict__ W2, const float* __restrict__ b2,
                const float* __restrict__ P2,
                float* __restrict__ out)
{
    __shared__ float sA[16][64];
    __shared__ float sW[16][256];
    __shared__ float red[8];

    const int bid = blockIdx.x;
    const int tid = threadIdx.x;

    // Zero recurrent states (deterministic per launch).
    for (int i = bid * 256 + tid; i < NLAYERS * BATCH * HDIM; i += NBLK * 256)
        ((float*)g_c)[i] = 0.0f;
    for (int i = bid * 256 + tid; i < NLAYERS * BATCH * PJDIM; i += NBLK * 256)
        ((float*)g_h)[i] = 0.0f;
    grid_barrier();

    for (int t = 0; t < T_STEPS; t++) {
        const float* xt = x + (size_t)t * BATCH * FDIM;

        gates_tile<FDIM, true>(xt, g_h[0], W0, b0, g_c[0], sA, sW);
        grid_barrier();
        proj_tile(P0, g_h[0], sA, sW);
        grid_barrier();

        gates_tile<PJDIM, false>(g_h[0], g_h[1], W1, b1, g_c[1], sA, sW);
        grid_barrier();
        proj_tile(P1, g_h[1], sA, sW);
        grid_barrier();

        gates_tile<PJDIM, false>(g_h[1], g_h[2], W2, b2, g_c[2], sA, sW);
        grid_barrier();
        proj_tile(P2, g_h[2], sA, sW);
        grid_barrier();
    }

    // L2 normalize last layer h at final step. 256 threads == PJDIM.
    for (int b = bid; b < BATCH; b += NBLK) {
        float v = __ldcg(&g_h[NLAYERS - 1][b * PJDIM + tid]);
        float s = v * v;
#pragma unroll
        for (int o = 16; o > 0; o >>= 1) s += __shfl_xor_sync(0xffffffffu, s, o);
        if ((tid & 31) == 0) red[tid >> 5] = s;
        __syncthreads();
        float tot = red[0] + red[1] + red[2] + red[3] +
                    red[4] + red[5] + red[6] + red[7];
        out[b * PJDIM + tid] = v * rsqrtf(fmaxf(tot, 1e-12f));
        __syncthreads();
    }
}

extern "C" void kernel_launch(void* const* d_in, const int* in_sizes, int n_in,
                              void* d_out, int out_size)
{
    const float* x  = (const float*)d_in[0];
    const float* W0 = (const float*)d_in[1];
    const float* b0 = (const float*)d_in[2];
    const float* P0 = (const float*)d_in[3];
    const float* W1 = (const float*)d_in[4];
    const float* b1 = (const float*)d_in[5];
    const float* P1 = (const float*)d_in[6];
    const float* W2 = (const float*)d_in[7];
    const float* b2 = (const float*)d_in[8];
    const float* P2 = (const float*)d_in[9];
    float* out = (float*)d_out;
    (void)in_sizes; (void)n_in; (void)out_size;

    lstm_persistent<<<NBLK, 256>>>(x, W0, b0, P0, W1, b1, P1, W2, b2, P2, out);
}

// round 3
// speedup vs baseline: 1.5605x; 1.5605x over previous
#include <cuda_runtime.h>
#include <math.h>

#define T_STEPS 160
#define BATCH   640
#define FDIM    40
#define HDIM    768
#define PJDIM   256
#define NLAYERS 3
#define NBLK    120   // <= 148 SMs: all blocks co-resident, grid barrier safe

typedef unsigned long long ull;

// Persistent recurrent state (scratch) — __device__ globals per harness rules.
__device__ float g_c[NLAYERS][BATCH * HDIM];    // cell states
__device__ float g_m[NLAYERS][BATCH * HDIM];    // pre-projection outputs (per layer)
__device__ float g_h[NLAYERS][BATCH * PJDIM];   // projected states
__device__ unsigned g_bar_count;
__device__ unsigned g_bar_gen;

__device__ __forceinline__ float sigf(float x) { return 1.0f / (1.0f + __expf(-x)); }

// Packed fp32x2 FMA (Blackwell FFMA2): 2 IEEE fp32 FMAs per instruction.
__device__ __forceinline__ void ffma2(ull& acc, ull a, ull b) {
    asm("fma.rn.f32x2 %0, %1, %2, %0;" : "+l"(acc) : "l"(a), "l"(b));
}
__device__ __forceinline__ ull pack2(float lo, float hi) {
    ull r; asm("mov.b64 %0, {%1, %2};" : "=l"(r) : "f"(lo), "f"(hi)); return r;
}
__device__ __forceinline__ void unpack2(ull v, float& lo, float& hi) {
    asm("mov.b64 {%0, %1}, %2;" : "=f"(lo), "=f"(hi) : "l"(v));
}

// Software grid barrier (all NBLK blocks resident).
__device__ __forceinline__ void grid_barrier() {
    __syncthreads();
    if (threadIdx.x == 0) {
        __threadfence();
        unsigned gen = *(volatile unsigned*)&g_bar_gen;
        if (atomicAdd(&g_bar_count, 1u) == NBLK - 1) {
            g_bar_count = 0;
            __threadfence();
            atomicAdd(&g_bar_gen, 1u);
        } else {
            while (*(volatile unsigned*)&g_bar_gen == gen) { __nanosleep(64); }
        }
        __threadfence();
    }
    __syncthreads();
}

// ---------------- gates GEMM + LSTM cell update -------------------------------
// Tile: 64 rows x 64 gate-cols (x4 gates). 120 tiles -> 1 per block.
// Double-buffered smem, one __syncthreads per K-chunk, FFMA2 inner loop.
template <int XK, bool XCONST>
__device__ void gates_tile(const float* __restrict__ xpart,
                           const float* __restrict__ hprev,
                           const float* __restrict__ W,
                           const float* __restrict__ bias,
                           float* __restrict__ c,
                           float* __restrict__ m,
                           float (&sA)[2][16][64],
                           float (&sW)[2][16][256])
{
    constexpr int K  = XK + PJDIM;
    constexpr int NC = (K + 15) / 16;

    const int tid = threadIdx.x;
    const int bid = blockIdx.x;
    const int ty  = tid >> 5;
    const int tx  = tid & 31;
    const int m0  = (bid % 10) * 64;
    const int n0  = (bid / 10) * 64;
    const int wcol = n0 + (tid >> 6) * HDIM + (tid & 63);

    ull acc2[4][8];
#pragma unroll
    for (int g = 0; g < 4; g++)
#pragma unroll
        for (int i = 0; i < 8; i++) acc2[g][i] = 0ull;

    float rA[4], rW[16];

    // ---- load helpers (chunk ch) ----
    auto loadA = [&](int ch) {
#pragma unroll
        for (int e = 0; e < 4; e++) {
            int idx = tid * 4 + e;
            int r   = idx >> 4;
            int kg  = ch * 16 + (idx & 15);
            float v;
            if (kg < XK) {
                v = XCONST ? __ldg(&xpart[(m0 + r) * XK + kg])
                           : __ldcg(&xpart[(m0 + r) * XK + kg]);
            } else if (kg < K) {
                v = __ldcg(&hprev[(m0 + r) * PJDIM + (kg - XK)]);
            } else v = 0.0f;
            rA[e] = v;
        }
    };
    auto loadW = [&](int ch) {
#pragma unroll
        for (int kk = 0; kk < 16; kk++) {
            int kg = ch * 16 + kk;
            rW[kk] = (kg < K) ? __ldg(&W[kg * (4 * HDIM) + wcol]) : 0.0f;
        }
    };
    auto stsAB = [&](int buf) {
#pragma unroll
        for (int e = 0; e < 4; e++) {
            int idx = tid * 4 + e;
            sA[buf][idx & 15][idx >> 4] = rA[e];
        }
#pragma unroll
        for (int kk = 0; kk < 16; kk++) sW[buf][kk][tid] = rW[kk];
    };

    loadA(0); loadW(0);
    stsAB(0);
    __syncthreads();

    for (int ch = 0; ch < NC; ch++) {
        int buf = ch & 1;
        if (ch + 1 < NC) { loadA(ch + 1); loadW(ch + 1); }

#pragma unroll
        for (int kk = 0; kk < 16; kk++) {
            ull a2[8];
#pragma unroll
            for (int i = 0; i < 8; i++) {
                float a = sA[buf][kk][ty * 8 + i];
                a2[i] = pack2(a, a);
            }
#pragma unroll
            for (int g = 0; g < 4; g++) {
                ull w2 = *(const ull*)&sW[buf][kk][g * 64 + tx * 2];
#pragma unroll
                for (int i = 0; i < 8; i++) ffma2(acc2[g][i], a2[i], w2);
            }
        }

        if (ch + 1 < NC) stsAB(buf ^ 1);
        __syncthreads();
    }

    // Epilogue: cell update (fp32 exact)
    {
        int n = n0 + tx * 2;
        float bi0 = __ldg(&bias[n]),            bi1 = __ldg(&bias[n + 1]);
        float bj0 = __ldg(&bias[n + HDIM]),     bj1 = __ldg(&bias[n + HDIM + 1]);
        float bf0 = __ldg(&bias[n + 2 * HDIM]), bf1 = __ldg(&bias[n + 2 * HDIM + 1]);
        float bo0 = __ldg(&bias[n + 3 * HDIM]), bo1 = __ldg(&bias[n + 3 * HDIM + 1]);
#pragma unroll
        for (int i = 0; i < 8; i++) {
            int row = m0 + ty * 8 + i;
            float zi0, zi1, zj0, zj1, zf0, zf1, zo0, zo1;
            unpack2(acc2[0][i], zi0, zi1);
            unpack2(acc2[1][i], zj0, zj1);
            unpack2(acc2[2][i], zf0, zf1);
            unpack2(acc2[3][i], zo0, zo1);
            zi0 += bi0; zi1 += bi1; zj0 += bj0; zj1 += bj1;
            zf0 += bf0; zf1 += bf1; zo0 += bo0; zo1 += bo1;

            float c0 = c[row * HDIM + n];
            float c1 = c[row * HDIM + n + 1];
            float cn0 = sigf(zf0 + 1.0f) * c0 + sigf(zi0) * tanhf(zj0);
            float cn1 = sigf(zf1 + 1.0f) * c1 + sigf(zi1) * tanhf(zj1);
            float mm0 = sigf(zo0) * tanhf(cn0);
            float mm1 = sigf(zo1) * tanhf(cn1);
            c[row * HDIM + n]     = cn0;
            c[row * HDIM + n + 1] = cn1;
            m[row * HDIM + n]     = mm0;
            m[row * HDIM + n + 1] = mm1;
        }
    }
}

// ---------------- projection GEMM: h = m @ P (640x256x768) --------------------
// Tile 64 rows x 32 cols -> 80 tiles/layer; 240 jobs over 120 blocks (2 each).
__device__ void proj_tile(const float* __restrict__ mbuf,
                          const float* __restrict__ P,
                          float* __restrict__ h,
                          int tile,
                          float (&sA)[2][16][64],
                          float (&sW)[2][16][256])
{
    const int tid = threadIdx.x;
    const int ty  = tid >> 4;   // 0..15, 4 rows each
    const int tx  = tid & 15;   // 0..15, 2 cols each
    const int m0  = (tile % 10) * 64;
    const int n0  = (tile / 10) * 32;
    constexpr int NC = HDIM / 16;   // 48

    ull acc2[4];
#pragma unroll
    for (int i = 0; i < 4; i++) acc2[i] = 0ull;

    float rA[4], rW[2];

    auto loadA = [&](int ch) {
#pragma unroll
        for (int e = 0; e < 4; e++) {
            int idx = tid * 4 + e;
            int r   = idx >> 4;
            int kg  = ch * 16 + (idx & 15);
            rA[e] = __ldcg(&mbuf[(m0 + r) * HDIM + kg]);
        }
    };
    auto loadW = [&](int ch) {
#pragma unroll
        for (int e = 0; e < 2; e++) {
            int idx = tid + e * 256;
            int kk  = idx >> 5;
            int cc  = idx & 31;
            rW[e] = __ldg(&P[(ch * 16 + kk) * PJDIM + n0 + cc]);
        }
    };
    auto stsAB = [&](int buf) {
#pragma unroll
        for (int e = 0; e < 4; e++) {
            int idx = tid * 4 + e;
            sA[buf][idx & 15][idx >> 4] = rA[e];
        }
#pragma unroll
        for (int e = 0; e < 2; e++) {
            int idx = tid + e * 256;
            sW[buf][idx >> 5][idx & 31] = rW[e];
        }
    };

    loadA(0); loadW(0);
    stsAB(0);
    __syncthreads();

    for (int ch = 0; ch < NC; ch++) {
        int buf = ch & 1;
        if (ch + 1 < NC) { loadA(ch + 1); loadW(ch + 1); }

#pragma unroll
        for (int kk = 0; kk < 16; kk++) {
            ull w2 = *(const ull*)&sW[buf][kk][tx * 2];
#pragma unroll
            for (int i = 0; i < 4; i++) {
                float a = sA[buf][kk][ty * 4 + i];
                ffma2(acc2[i], pack2(a, a), w2);
            }
        }

        if (ch + 1 < NC) stsAB(buf ^ 1);
        __syncthreads();
    }

#pragma unroll
    for (int i = 0; i < 4; i++) {
        int row = m0 + ty * 4 + i;
        float lo, hi;
        unpack2(acc2[i], lo, hi);
        h[row * PJDIM + n0 + tx * 2]     = lo;
        h[row * PJDIM + n0 + tx * 2 + 1] = hi;
    }
}

// ---------------- persistent driver: layer-time wavefront ---------------------
__global__ void __launch_bounds__(256)
lstm_persistent(const float* __restrict__ x,
                const float* __restrict__ W0, const float* __restrict__ b0,
                const float* __restrict__ P0,
                const float* __restrict__ W1, const float* __restrict__ b1,
                const float* __restrict__ P1,
                const float* __restrict__ W2, const float* __restrict__ b2,
                const float* __restrict__ P2,
                float* __restrict__ out)
{
    __shared__ float sA[2][16][64];
    __shared__ float sW[2][16][256];
    __shared__ float red[8];

    const int bid = blockIdx.x;
    const int tid = threadIdx.x;

    for (int i = bid * 256 + tid; i < NLAYERS * BATCH * HDIM; i += NBLK * 256)
        ((float*)g_c)[i] = 0.0f;
    for (int i = bid * 256 + tid; i < NLAYERS * BATCH * PJDIM; i += NBLK * 256)
        ((float*)g_h)[i] = 0.0f;
    grid_barrier();

    const float* Ps[NLAYERS] = {P0, P1, P2};

    // Wavefront: at step s compute gates/proj for (L0,s), (L1,s-1), (L2,s-2).
    for (int s = 0; s < T_STEPS + 2; s++) {
        // ---- phase A: gates for all valid layers (each block: its tile x3) ----
        if (s < T_STEPS) {
            const float* xt = x + (size_t)s * BATCH * FDIM;
            gates_tile<FDIM, true>(xt, g_h[0], W0, b0, g_c[0], g_m[0], sA, sW);
        }
        if (s >= 1 && s - 1 < T_STEPS)
            gates_tile<PJDIM, false>(g_h[0], g_h[1], W1, b1, g_c[1], g_m[1], sA, sW);
        if (s >= 2 && s - 2 < T_STEPS)
            gates_tile<PJDIM, false>(g_h[1], g_h[2], W2, b2, g_c[2], g_m[2], sA, sW);
        grid_barrier();

        // ---- phase B: projections, 240 jobs (3 layers x 80 tiles) over 120 blocks
#pragma unroll
        for (int q = 0; q < 2; q++) {
            int job   = bid + q * NBLK;
            int layer = job / 80;
            int tile  = job % 80;
            int tL    = s - layer;
            if (tL >= 0 && tL < T_STEPS)
                proj_tile(g_m[layer], Ps[layer], g_h[layer], tile, sA, sW);
        }
        grid_barrier();
    }

    // L2 normalize h2 at final step.
    for (int b = bid; b < BATCH; b += NBLK) {
        float v = __ldcg(&g_h[NLAYERS - 1][b * PJDIM + tid]);
        float sm = v * v;
#pragma unroll
        for (int o = 16; o > 0; o >>= 1) sm += __shfl_xor_sync(0xffffffffu, sm, o);
        if ((tid & 31) == 0) red[tid >> 5] = sm;
        __syncthreads();
        float tot = red[0] + red[1] + red[2] + red[3] +
                    red[4] + red[5] + red[6] + red[7];
        out[b * PJDIM + tid] = v * rsqrtf(fmaxf(tot, 1e-12f));
        __syncthreads();
    }
}

extern "C" void kernel_launch(void* const* d_in, const int* in_sizes, int n_in,
                              void* d_out, int out_size)
{
    const float* x  = (const float*)d_in[0];
    const float* W0 = (const float*)d_in[1];
    const float* b0 = (const float*)d_in[2];
    const float* P0 = (const float*)d_in[3];
    const float* W1 = (const float*)d_in[4];
    const float* b1 = (const float*)d_in[5];
    const float* P1 = (const float*)d_in[6];
    const float* W2 = (const float*)d_in[7];
    const float* b2 = (const float*)d_in[8];
    const float* P2 = (const float*)d_in[9];
    float* out = (float*)d_out;
    (void)in_sizes; (void)n_in; (void)out_size;

    lstm_persistent<<<NBLK, 256>>>(x, W0, b0, P0, W1, b1, P1, W2, b2, P2, out);
}

// round 4
// speedup vs baseline: 2.8339x; 1.8160x over previous
#include <cuda_runtime.h>
#include <math.h>
#include <stdint.h>

#define T_STEPS 160
#define BATCH   640
#define FDIM    40
#define HDIM    768
#define PJDIM   256
#define NLAYERS 3
#define NBLK    120
#define KCH     16

#define NCH0    19      // ceil(296/16)
#define NCH12   32      // 512/16
#define K0      296
#define K12     512

// ---------------- device globals (scratch; no allocation allowed) -------------
__device__ float g_c[NLAYERS][HDIM * BATCH];   // c_perm[gcol*640+row]
__device__ float g_m[NLAYERS][HDIM * BATCH];   // m_perm[gcol*640+row]
__device__ float g_h[NLAYERS][BATCH * PJDIM];  // row-major [row][256]
__device__ unsigned g_bar_count;
__device__ unsigned g_bar_gen;

// Pre-swizzled tf32 weights
__device__ uint32_t g_W0pre[12 * NCH0  * 128 * 32];   // 933,888
__device__ uint32_t g_W1pre[12 * NCH12 * 128 * 32];   // 1,572,864
__device__ uint32_t g_W2pre[12 * NCH12 * 128 * 32];
__device__ uint32_t g_Ppre [3 * 4 * 48 * 32 * 32];    // 589,824

__device__ __forceinline__ float sigf(float x) { return 1.0f / (1.0f + __expf(-x)); }

__device__ __forceinline__ uint32_t f2tf32(float f) {
    uint32_t r; asm("cvt.rna.tf32.f32 %0, %1;" : "=r"(r) : "f"(f)); return r;
}

__device__ __forceinline__ void mma_tf32(float& c0, float& c1, float& c2, float& c3,
                                         uint32_t a0, uint32_t a1, uint32_t a2, uint32_t a3,
                                         uint32_t b0, uint32_t b1) {
    asm("mma.sync.aligned.m16n8k8.row.col.f32.tf32.tf32.f32 "
        "{%0,%1,%2,%3},{%4,%5,%6,%7},{%8,%9},{%0,%1,%2,%3};"
        : "+f"(c0), "+f"(c1), "+f"(c2), "+f"(c3)
        : "r"(a0), "r"(a1), "r"(a2), "r"(a3), "r"(b0), "r"(b1));
}

__device__ __forceinline__ void grid_barrier() {
    __syncthreads();
    if (threadIdx.x == 0) {
        __threadfence();
        unsigned gen = *(volatile unsigned*)&g_bar_gen;
        if (atomicAdd(&g_bar_count, 1u) == NBLK - 1) {
            g_bar_count = 0;
            __threadfence();
            atomicAdd(&g_bar_gen, 1u);
        } else {
            while (*(volatile unsigned*)&g_bar_gen == gen) { __nanosleep(64); }
        }
        __threadfence();
    }
    __syncthreads();
}

// ---------------- weight precompute: tf32 convert + swizzle -------------------
// Gates W_pre unit: u in [0,128): col=(u&31)*8+(lane>>2) (gate-interleaved block col),
// kk=(u>>5)*4+(lane&3). Block col c: gate=c&3, cc=c>>2; wcol=g*768+nt*64+cc.
__device__ void prep_w(uint32_t* dst, const float* W, int uw, int lane, int NCH, int K) {
    int nt  = uw / (NCH * 128);
    int rem = uw % (NCH * 128);
    int ch  = rem / 128;
    int u   = rem % 128;
    int col = (u & 31) * 8 + (lane >> 2);
    int kk  = (u >> 5) * 4 + (lane & 3);
    int k   = ch * KCH + kk;
    int g   = col & 3, cc = col >> 2;
    float v = (k < K) ? W[k * (4 * HDIM) + g * HDIM + nt * 64 + cc] : 0.0f;
    dst[(size_t)uw * 32 + lane] = f2tf32(v);
}

__global__ void precompute_weights(const float* __restrict__ W0, const float* __restrict__ W1,
                                   const float* __restrict__ W2, const float* __restrict__ P0,
                                   const float* __restrict__ P1, const float* __restrict__ P2)
{
    int wg   = (blockIdx.x * blockDim.x + threadIdx.x) >> 5;
    int lane = threadIdx.x & 31;
    const int NW0 = 12 * NCH0 * 128;          // 29184
    const int NW12 = 12 * NCH12 * 128;        // 49152
    if (wg < NW0) { prep_w(g_W0pre, W0, wg, lane, NCH0, K0); return; }
    wg -= NW0;
    if (wg < NW12) { prep_w(g_W1pre, W1, wg, lane, NCH12, K12); return; }
    wg -= NW12;
    if (wg < NW12) { prep_w(g_W2pre, W2, wg, lane, NCH12, K12); return; }
    wg -= NW12;
    // P: 3 layers x (4 ntiles x 48 ch x 32 units)
    if (wg < 3 * 4 * 48 * 32) {
        int layer = wg / (4 * 48 * 32);
        int rem   = wg % (4 * 48 * 32);
        int nt    = rem / (48 * 32);
        int r3    = rem % (48 * 32);
        int ch    = r3 / 32;
        int u     = r3 % 32;
        int col   = (u & 7) * 8 + (lane >> 2);
        int kk    = (u >> 3) * 4 + (lane & 3);
        int k     = ch * KCH + kk;
        const float* P = (layer == 0) ? P0 : (layer == 1) ? P1 : P2;
        g_Ppre[(size_t)layer * 196608 + ((size_t)(nt * 48 + ch) * 32 + u) * 32 + lane] =
            f2tf32(P[k * PJDIM + nt * 64 + col]);
    }
}

// ---------------- gates: 64x256 tile tf32 mma + fused cell update -------------
// Block: m0=(bid%10)*64 rows, ntile=bid/10 (64 gate-cols, x4 gates interleaved).
// 8 warps = 2x4 (warp tile 32x64). smem: sA[2][64][20], sW[2][256][20] (conflict-free).
template <int XK, int NCH, bool XCONST>
__device__ void gates_mma(const float* __restrict__ xA,   // [row][XK]
                          const float* __restrict__ hA,   // [row][256]
                          const uint32_t* __restrict__ Wlayer,
                          const float* __restrict__ bias,
                          float* __restrict__ cbuf, float* __restrict__ mbuf,
                          uint32_t* __restrict__ sA, uint32_t* __restrict__ sW)
{
    constexpr int K = XK + PJDIM;
    const int tid = threadIdx.x, lane = tid & 31, wid = tid >> 5;
    const int bid = blockIdx.x;
    const int m0  = (bid % 10) * 64;
    const int nt0 = bid / 10;
    const uint32_t* Wp = Wlayer + (size_t)nt0 * NCH * 4096;
    const int wm = wid >> 2, wn = wid & 3;
    const int grp = lane >> 2, q = lane & 3;

    float acc[2][8][4];
#pragma unroll
    for (int mt = 0; mt < 2; mt++)
#pragma unroll
        for (int nt = 0; nt < 8; nt++)
#pragma unroll
            for (int r = 0; r < 4; r++) acc[mt][nt][r] = 0.0f;

    float ra[4]; uint32_t rw[16];
    const int arow = tid >> 4;   // +e*16
    const int akk  = tid & 15;

    auto ldA = [&](int ch) {
#pragma unroll
        for (int e = 0; e < 4; e++) {
            int row = e * 16 + arow;
            int kg  = ch * KCH + akk;
            float v;
            if (kg < XK)      v = XCONST ? __ldg(&xA[(m0 + row) * XK + kg])
                                         : __ldcg(&xA[(m0 + row) * XK + kg]);
            else if (kg < K)  v = __ldcg(&hA[(m0 + row) * PJDIM + (kg - XK)]);
            else              v = 0.0f;
            ra[e] = v;
        }
    };
    auto ldW = [&](int ch) {
        const uint32_t* p = Wp + (size_t)ch * 4096 + wid * 512 + lane;
#pragma unroll
        for (int e = 0; e < 16; e++) rw[e] = __ldg(&p[e * 32]);
    };
    auto stA = [&](int buf) {
#pragma unroll
        for (int e = 0; e < 4; e++)
            sA[buf * 1280 + (e * 16 + arow) * 20 + akk] = f2tf32(ra[e]);
    };
    auto stW = [&](int buf) {
        int colb = (wid & 1) * 16;
        int kkb  = (wid >> 1) * 4 + q;
#pragma unroll
        for (int e = 0; e < 16; e++)
            sW[buf * 5120 + ((colb + e) * 8 + grp) * 20 + kkb] = rw[e];
    };

    ldA(0); ldW(0);
    stA(0); stW(0);
    __syncthreads();

    for (int ch = 0; ch < NCH; ch++) {
        int buf = ch & 1;
        if (ch + 1 < NCH) { ldA(ch + 1); ldW(ch + 1); }
        const uint32_t* bA = sA + buf * 1280;
        const uint32_t* bW = sW + buf * 5120;
#pragma unroll
        for (int s = 0; s < 2; s++) {
            uint32_t a[2][4];
#pragma unroll
            for (int mt = 0; mt < 2; mt++) {
                int r = wm * 32 + mt * 16 + grp;
                a[mt][0] = bA[r * 20 + s * 8 + q];
                a[mt][1] = bA[(r + 8) * 20 + s * 8 + q];
                a[mt][2] = bA[r * 20 + s * 8 + q + 4];
                a[mt][3] = bA[(r + 8) * 20 + s * 8 + q + 4];
            }
#pragma unroll
            for (int nt = 0; nt < 8; nt++) {
                int col = wn * 64 + nt * 8 + grp;
                uint32_t b0 = bW[col * 20 + s * 8 + q];
                uint32_t b1 = bW[col * 20 + s * 8 + q + 4];
#pragma unroll
                for (int mt = 0; mt < 2; mt++)
                    mma_tf32(acc[mt][nt][0], acc[mt][nt][1], acc[mt][nt][2], acc[mt][nt][3],
                             a[mt][0], a[mt][1], a[mt][2], a[mt][3], b0, b1);
            }
        }
        if (ch + 1 < NCH) { stA(buf ^ 1); stW(buf ^ 1); }
        __syncthreads();
    }

    // Epilogue: lane pair (lane^1) jointly owns all 4 gates of one cell column.
    const int gc0 = nt0 * 64;
    const int p = lane & 1;
#pragma unroll
    for (int nt = 0; nt < 8; nt++) {
        int cc = wn * 16 + 2 * nt + (q >> 1);
        int gc = gc0 + cc;
        float bi = __ldg(&bias[gc]);
        float bj = __ldg(&bias[gc + HDIM]);
        float bf = __ldg(&bias[gc + 2 * HDIM]);
        float bo = __ldg(&bias[gc + 3 * HDIM]);
#pragma unroll
        for (int mt = 0; mt < 2; mt++) {
            float c0 = acc[mt][nt][0], c1 = acc[mt][nt][1];
            float c2 = acc[mt][nt][2], c3 = acc[mt][nt][3];
            float v = __shfl_xor_sync(0xffffffffu, p ? c0 : c2, 1);
            float w = __shfl_xor_sync(0xffffffffu, p ? c1 : c3, 1);
            float zi, zj, zf, zo;
            if (p == 0) { zi = c0; zj = c1; zf = v;  zo = w;  }   // row grp
            else        { zi = v;  zj = w;  zf = c2; zo = c3; }   // row grp+8
            int row = m0 + wm * 32 + mt * 16 + grp + (p ? 8 : 0);
            zi += bi; zj += bj; zf += bf; zo += bo;
            float cold = cbuf[gc * BATCH + row];
            float cn = sigf(zf + 1.0f) * cold + sigf(zi) * tanhf(zj);
            float mm = sigf(zo) * tanhf(cn);
            cbuf[gc * BATCH + row] = cn;
            mbuf[gc * BATCH + row] = mm;
        }
    }
}

// ---------------- projection: 32x64 tile, h = m @ P ---------------------------
// 80 tiles/layer: tile%20 -> m0, tile/20 -> 64-col group. 8 warps = 2x4 (16x16 each).
__device__ void proj_mma(const float* __restrict__ mperm,
                         const uint32_t* __restrict__ Players,
                         float* __restrict__ hout, int tile,
                         uint32_t* __restrict__ sA, uint32_t* __restrict__ sW)
{
    const int tid = threadIdx.x, lane = tid & 31, wid = tid >> 5;
    const int m0  = (tile % 20) * 32;
    const int nt4 = tile / 20;
    const uint32_t* Pb = Players + (size_t)nt4 * 48 * 1024;
    const int wm = wid >> 2, wn = wid & 3;
    const int grp = lane >> 2, q = lane & 3;

    float acc[2][4];
#pragma unroll
    for (int nt = 0; nt < 2; nt++)
#pragma unroll
        for (int r = 0; r < 4; r++) acc[nt][r] = 0.0f;

    float ra[2]; uint32_t rw[4];

    auto ldA = [&](int ch) {
#pragma unroll
        for (int e = 0; e < 2; e++) {
            int kk = e * 8 + wid;
            ra[e] = __ldcg(&mperm[(ch * KCH + kk) * BATCH + m0 + lane]);
        }
    };
    auto stA = [&](int buf) {
#pragma unroll
        for (int e = 0; e < 2; e++)
            sA[buf * 1280 + lane * 20 + e * 8 + wid] = f2tf32(ra[e]);
    };
    auto ldW = [&](int ch) {
        const uint32_t* pp = Pb + ch * 1024 + wid * 128 + lane;
#pragma unroll
        for (int e = 0; e < 4; e++) rw[e] = __ldg(&pp[e * 32]);
    };
    auto stW = [&](int buf) {
#pragma unroll
        for (int e = 0; e < 4; e++) {
            int u = wid * 4 + e;
            sW[buf * 5120 + ((u & 7) * 8 + grp) * 20 + (u >> 3) * 4 + q] = rw[e];
        }
    };

    ldA(0); ldW(0);
    stA(0); stW(0);
    __syncthreads();

    for (int ch = 0; ch < 48; ch++) {
        int buf = ch & 1;
        if (ch + 1 < 48) { ldA(ch + 1); ldW(ch + 1); }
        const uint32_t* bA = sA + buf * 1280;
        const uint32_t* bW = sW + buf * 5120;
#pragma unroll
        for (int s = 0; s < 2; s++) {
            int r = wm * 16 + grp;
            uint32_t a0 = bA[r * 20 + s * 8 + q];
            uint32_t a1 = bA[(r + 8) * 20 + s * 8 + q];
            uint32_t a2 = bA[r * 20 + s * 8 + q + 4];
            uint32_t a3 = bA[(r + 8) * 20 + s * 8 + q + 4];
#pragma unroll
            for (int nt = 0; nt < 2; nt++) {
                int col = wn * 16 + nt * 8 + grp;
                uint32_t b0 = bW[col * 20 + s * 8 + q];
                uint32_t b1 = bW[col * 20 + s * 8 + q + 4];
                mma_tf32(acc[nt][0], acc[nt][1], acc[nt][2], acc[nt][3],
                         a0, a1, a2, a3, b0, b1);
            }
        }
        if (ch + 1 < 48) { stA(buf ^ 1); stW(buf ^ 1); }
        __syncthreads();
    }

#pragma unroll
    for (int nt = 0; nt < 2; nt++) {
        int colb = nt4 * 64 + wn * 16 + nt * 8 + 2 * q;
        int row  = m0 + wm * 16 + grp;
        hout[row * PJDIM + colb]           = acc[nt][0];
        hout[row * PJDIM + colb + 1]       = acc[nt][1];
        hout[(row + 8) * PJDIM + colb]     = acc[nt][2];
        hout[(row + 8) * PJDIM + colb + 1] = acc[nt][3];
    }
}

// ---------------- persistent driver -------------------------------------------
__global__ void __launch_bounds__(256, 1)
lstm_persistent(const float* __restrict__ x,
                const float* __restrict__ b0, const float* __restrict__ b1,
                const float* __restrict__ b2,
                float* __restrict__ out)
{
    extern __shared__ uint32_t dynsmem[];
    uint32_t* sA = dynsmem;            // [2][64][20]
    uint32_t* sW = dynsmem + 2560;     // [2][256][20]
    __shared__ float red[8];

    const int bid = blockIdx.x;
    const int tid = threadIdx.x;

    for (int i = bid * 256 + tid; i < NLAYERS * HDIM * BATCH; i += NBLK * 256)
        ((float*)g_c)[i] = 0.0f;
    for (int i = bid * 256 + tid; i < NLAYERS * BATCH * PJDIM; i += NBLK * 256)
        ((float*)g_h)[i] = 0.0f;
    grid_barrier();

    for (int s = 0; s < T_STEPS + 2; s++) {
        // phase A: gates (wavefront: layer l at time s-l)
        if (s < T_STEPS)
            gates_mma<FDIM, NCH0, true>(x + (size_t)s * BATCH * FDIM, g_h[0],
                                        g_W0pre, b0, g_c[0], g_m[0], sA, sW);
        if (s >= 1 && s - 1 < T_STEPS)
            gates_mma<PJDIM, NCH12, false>(g_h[0], g_h[1], g_W1pre, b1,
                                           g_c[1], g_m[1], sA, sW);
        if (s >= 2 && s - 2 < T_STEPS)
            gates_mma<PJDIM, NCH12, false>(g_h[1], g_h[2], g_W2pre, b2,
                                           g_c[2], g_m[2], sA, sW);
        grid_barrier();

        // phase B: projections, 240 jobs (3 layers x 80 tiles) over 120 blocks
#pragma unroll
        for (int qj = 0; qj < 2; qj++) {
            int job   = bid + qj * NBLK;
            int layer = job / 80;
            int tile  = job % 80;
            if (s - layer >= 0 && s - layer < T_STEPS)
                proj_mma(g_m[layer], g_Ppre + (size_t)layer * 196608,
                         g_h[layer], tile, sA, sW);
        }
        grid_barrier();
    }

    // L2 normalize final h2
    for (int b = bid; b < BATCH; b += NBLK) {
        float v = __ldcg(&g_h[NLAYERS - 1][b * PJDIM + tid]);
        float sm = v * v;
#pragma unroll
        for (int o = 16; o > 0; o >>= 1) sm += __shfl_xor_sync(0xffffffffu, sm, o);
        if ((tid & 31) == 0) red[tid >> 5] = sm;
        __syncthreads();
        float tot = red[0] + red[1] + red[2] + red[3] +
                    red[4] + red[5] + red[6] + red[7];
        out[b * PJDIM + tid] = v * rsqrtf(fmaxf(tot, 1e-12f));
        __syncthreads();
    }
}

extern "C" void kernel_launch(void* const* d_in, const int* in_sizes, int n_in,
                              void* d_out, int out_size)
{
    const float* x  = (const float*)d_in[0];
    const float* W0 = (const float*)d_in[1];
    const float* b0 = (const float*)d_in[2];
    const float* P0 = (const float*)d_in[3];
    const float* W1 = (const float*)d_in[4];
    const float* b1 = (const float*)d_in[5];
    const float* P1 = (const float*)d_in[6];
    const float* W2 = (const float*)d_in[7];
    const float* b2 = (const float*)d_in[8];
    const float* P2 = (const float*)d_in[9];
    float* out = (float*)d_out;
    (void)in_sizes; (void)n_in; (void)out_size;

    cudaFuncSetAttribute(lstm_persistent,
                         cudaFuncAttributeMaxDynamicSharedMemorySize, 51200);

    // total warps: 29184 + 2*49152 + 18432 = 145920 -> 18240 blocks @256
    precompute_weights<<<18240, 256>>>(W0, W1, W2, P0, P1, P2);
    lstm_persistent<<<NBLK, 256, 51200>>>(x, b0, b1, b2, out);
}

// round 5
// speedup vs baseline: 3.2373x; 1.1424x over previous
#include <cuda_runtime.h>
#include <math.h>
#include <stdint.h>

#define T_STEPS 160
#define BATCH   640
#define FDIM    40
#define HDIM    768
#define PJDIM   256
#define NLAYERS 3
#define NBLK    120

#define NCH0    19
#define NCH12   32
#define K0      296
#define K12     512

// ---------------- device globals ----------------------------------------------
__device__ float g_c[NLAYERS][HDIM * BATCH];   // c_perm[gcol*640+row]
__device__ float g_m[NLAYERS][HDIM * BATCH];   // m_perm[gcol*640+row]
__device__ float g_h[NLAYERS][BATCH * PJDIM];  // row-major [row][256]
__device__ unsigned g_bar_count;
__device__ unsigned g_bar_gen;

// Pre-swizzled tf32 weights: gmem order == smem order (cp.async friendly).
// Gates chunk = 4096 words: word = s*2048 + col*8 + q*2 + hi  (col 0..255 gate-interleaved)
__device__ uint32_t g_W0pre[12 * NCH0  * 4096];
__device__ uint32_t g_W1pre[12 * NCH12 * 4096];
__device__ uint32_t g_W2pre[12 * NCH12 * 4096];
// Proj chunk = 1024 words: word = s*512 + col*8 + q*2 + hi (col 0..63)
__device__ uint32_t g_Ppre [3 * 4 * 48 * 1024];

__device__ __forceinline__ float sigf(float x) { return 1.0f / (1.0f + __expf(-x)); }

__device__ __forceinline__ uint32_t f2tf32(float f) {
    uint32_t r; asm("cvt.rna.tf32.f32 %0, %1;" : "=r"(r) : "f"(f)); return r;
}

__device__ __forceinline__ void mma_tf32(float& c0, float& c1, float& c2, float& c3,
                                         uint32_t a0, uint32_t a1, uint32_t a2, uint32_t a3,
                                         uint32_t b0, uint32_t b1) {
    asm("mma.sync.aligned.m16n8k8.row.col.f32.tf32.tf32.f32 "
        "{%0,%1,%2,%3},{%4,%5,%6,%7},{%8,%9},{%0,%1,%2,%3};"
        : "+f"(c0), "+f"(c1), "+f"(c2), "+f"(c3)
        : "r"(a0), "r"(a1), "r"(a2), "r"(a3), "r"(b0), "r"(b1));
}

__device__ __forceinline__ void cp16(uint32_t dst, const void* src) {
    asm volatile("cp.async.cg.shared.global [%0], [%1], 16;" :: "r"(dst), "l"(src));
}
#define CP_COMMIT() asm volatile("cp.async.commit_group;")
#define CP_WAIT0()  asm volatile("cp.async.wait_group 0;" ::: "memory")

__device__ __forceinline__ void grid_barrier() {
    __syncthreads();
    if (threadIdx.x == 0) {
        __threadfence();
        unsigned gen = *(volatile unsigned*)&g_bar_gen;
        if (atomicAdd(&g_bar_count, 1u) == NBLK - 1) {
            g_bar_count = 0;
            __threadfence();
            atomicAdd(&g_bar_gen, 1u);
        } else {
            while (*(volatile unsigned*)&g_bar_gen == gen) { __nanosleep(64); }
        }
        __threadfence();
    }
    __syncthreads();
}

// ---------------- weight precompute --------------------------------------------
// dst[idx]: idx = nt*(NCH*4096) + ch*4096 + gidx*4 + w
// gidx = s*512 + col*2 + g2 ; q = 2*g2 + (w>>1), hi = w&1 ; kk = s*8+q+4*hi
__device__ void prep_w(uint32_t* dst, const float* W, long idx, int NCH, int K) {
    int nt = (int)(idx / ((long)NCH * 4096));
    int r  = (int)(idx % ((long)NCH * 4096));
    int ch = r / 4096;
    int r2 = r % 4096;
    int gidx = r2 >> 2, w = r2 & 3;
    int s = gidx >> 9, col = (gidx >> 1) & 255, g2 = gidx & 1;
    int q = g2 * 2 + (w >> 1), hi = w & 1;
    int k = ch * 16 + s * 8 + q + hi * 4;
    int gate = col & 3, cc = col >> 2;
    float v = (k < K) ? W[k * (4 * HDIM) + gate * HDIM + nt * 64 + cc] : 0.0f;
    dst[idx] = f2tf32(v);
}

__global__ void precompute_weights(const float* __restrict__ W0, const float* __restrict__ W1,
                                   const float* __restrict__ W2, const float* __restrict__ P0,
                                   const float* __restrict__ P1, const float* __restrict__ P2)
{
    long idx = (long)blockIdx.x * 256 + threadIdx.x;
    const long NW0  = 12L * NCH0  * 4096;
    const long NW12 = 12L * NCH12 * 4096;
    if (idx < NW0)  { prep_w(g_W0pre, W0, idx, NCH0, K0);  return; }
    idx -= NW0;
    if (idx < NW12) { prep_w(g_W1pre, W1, idx, NCH12, K12); return; }
    idx -= NW12;
    if (idx < NW12) { prep_w(g_W2pre, W2, idx, NCH12, K12); return; }
    idx -= NW12;
    if (idx < 3L * 4 * 48 * 1024) {
        int save = (int)idx;
        int layer = (int)(idx / (4 * 48 * 1024));
        int r  = (int)(idx % (4 * 48 * 1024));
        int nt4 = r / (48 * 1024);
        int r2  = r % (48 * 1024);
        int ch  = r2 / 1024;
        int r3  = r2 % 1024;
        int gidx = r3 >> 2, w = r3 & 3;
        int s = gidx >> 7, col = (gidx >> 1) & 63, g2 = gidx & 1;
        int q = g2 * 2 + (w >> 1), hi = w & 1;
        int k = ch * 16 + s * 8 + q + hi * 4;
        const float* P = (layer == 0) ? P0 : (layer == 1) ? P1 : P2;
        g_Ppre[save] = f2tf32(P[k * PJDIM + nt4 * 64 + col]);
    }
}

// ---------------- gates: 64x256 tile + fused cell update -----------------------
// smem: sA[2][1024] (word = s*512 + row*8 + q*2 + hi), sW[2][4096] at word 2048.
template <int XK, int NCH, bool XCONST>
__device__ void gates_mma(const float* __restrict__ xA,
                          const float* __restrict__ hA,
                          const uint32_t* __restrict__ Wlayer,
                          const float* __restrict__ bias,
                          float* __restrict__ cbuf, float* __restrict__ mbuf,
                          uint32_t* __restrict__ sm, uint32_t sb)
{
    constexpr int K = XK + PJDIM;
    const int tid = threadIdx.x, lane = tid & 31, wid = tid >> 5;
    const int bid = blockIdx.x;
    const int m0  = (bid % 10) * 64;
    const int nt0 = bid / 10;
    const uint32_t* Wp = Wlayer + (size_t)nt0 * NCH * 4096;
    const int wm = wid >> 2, wn = wid & 3;
    const int grp = lane >> 2, q = lane & 3;
    const int arow = tid >> 2, aj = tid & 3;

    float acc[2][8][4];
#pragma unroll
    for (int mt = 0; mt < 2; mt++)
#pragma unroll
        for (int nt = 0; nt < 8; nt++)
#pragma unroll
            for (int r = 0; r < 4; r++) acc[mt][nt][r] = 0.0f;

    float4 ra;

    auto ldA = [&](int ch) {
        int kg = ch * 16 + aj * 4;
        if (kg < XK) {
            ra = XCONST ? __ldg((const float4*)&xA[(m0 + arow) * XK + kg])
                        : __ldcg((const float4*)&xA[(m0 + arow) * XK + kg]);
        } else if (kg < K) {
            ra = __ldcg((const float4*)&hA[(m0 + arow) * PJDIM + (kg - XK)]);
        } else {
            ra = make_float4(0.f, 0.f, 0.f, 0.f);
        }
    };
    auto stA = [&](int buf) {
        uint32_t* d = sm + buf * 1024 + (aj >> 1) * 512 + arow * 8 + (aj & 1);
        d[0] = f2tf32(ra.x); d[2] = f2tf32(ra.y);
        d[4] = f2tf32(ra.z); d[6] = f2tf32(ra.w);
    };
    auto ldW = [&](int ch, int buf) {
        const uint32_t* src = Wp + (size_t)ch * 4096 + tid * 4;
        uint32_t dst = sb + (2048 + buf * 4096 + tid * 4) * 4;
#pragma unroll
        for (int e = 0; e < 4; e++)
            cp16(dst + e * 4096, src + e * 1024);
        CP_COMMIT();
    };

    ldW(0, 0);
    ldA(0);
    stA(0);
    CP_WAIT0();
    __syncthreads();

    for (int ch = 0; ch < NCH; ch++) {
        int buf = ch & 1;
        bool more = (ch + 1 < NCH);
        if (more) { ldW(ch + 1, buf ^ 1); ldA(ch + 1); }

        const uint32_t* bA = sm + buf * 1024;
        const uint32_t* bW = sm + 2048 + buf * 4096;
#pragma unroll
        for (int s = 0; s < 2; s++) {
            uint2 a02[2], a13[2];
#pragma unroll
            for (int mt = 0; mt < 2; mt++) {
                int r = wm * 32 + mt * 16 + grp;
                a02[mt] = *(const uint2*)&bA[s * 512 + r * 8 + q * 2];
                a13[mt] = *(const uint2*)&bA[s * 512 + (r + 8) * 8 + q * 2];
            }
#pragma unroll
            for (int nt = 0; nt < 8; nt++) {
                int col = wn * 64 + nt * 8 + grp;
                uint2 b01 = *(const uint2*)&bW[s * 2048 + col * 8 + q * 2];
#pragma unroll
                for (int mt = 0; mt < 2; mt++)
                    mma_tf32(acc[mt][nt][0], acc[mt][nt][1], acc[mt][nt][2], acc[mt][nt][3],
                             a02[mt].x, a13[mt].x, a02[mt].y, a13[mt].y, b01.x, b01.y);
            }
        }
        if (more) stA(buf ^ 1);
        CP_WAIT0();
        __syncthreads();
    }

    // Epilogue (unchanged from R4): lane pair assembles (i,j,f,o).
    const int gc0 = nt0 * 64;
    const int p = lane & 1;
#pragma unroll
    for (int nt = 0; nt < 8; nt++) {
        int cc = wn * 16 + 2 * nt + (q >> 1);
        int gc = gc0 + cc;
        float bi = __ldg(&bias[gc]);
        float bj = __ldg(&bias[gc + HDIM]);
        float bf = __ldg(&bias[gc + 2 * HDIM]);
        float bo = __ldg(&bias[gc + 3 * HDIM]);
#pragma unroll
        for (int mt = 0; mt < 2; mt++) {
            float c0 = acc[mt][nt][0], c1 = acc[mt][nt][1];
            float c2 = acc[mt][nt][2], c3 = acc[mt][nt][3];
            float v = __shfl_xor_sync(0xffffffffu, p ? c0 : c2, 1);
            float w = __shfl_xor_sync(0xffffffffu, p ? c1 : c3, 1);
            float zi, zj, zf, zo;
            if (p == 0) { zi = c0; zj = c1; zf = v;  zo = w;  }
            else        { zi = v;  zj = w;  zf = c2; zo = c3; }
            int row = m0 + wm * 32 + mt * 16 + grp + (p ? 8 : 0);
            zi += bi; zj += bj; zf += bf; zo += bo;
            float cold = cbuf[gc * BATCH + row];
            float cn = sigf(zf + 1.0f) * cold + sigf(zi) * tanhf(zj);
            float mm = sigf(zo) * tanhf(cn);
            cbuf[gc * BATCH + row] = cn;
            mbuf[gc * BATCH + row] = mm;
        }
    }
}

// ---------------- projection: one 64x64 tile per block -------------------------
__device__ void proj_mma(const float* __restrict__ mperm,
                         const uint32_t* __restrict__ Pblk,  // per (layer, nt4)
                         float* __restrict__ hout,
                         int m0, int nt4,
                         uint32_t* __restrict__ sm, uint32_t sb)
{
    const int tid = threadIdx.x, lane = tid & 31, wid = tid >> 5;
    const int wm = wid >> 2, wn = wid & 3;
    const int grp = lane >> 2, q = lane & 3;
    const int klocal = tid >> 4;           // 0..15
    const int row4 = (tid & 15) * 4;

    float acc[2][2][4];
#pragma unroll
    for (int mt = 0; mt < 2; mt++)
#pragma unroll
        for (int nt = 0; nt < 2; nt++)
#pragma unroll
            for (int r = 0; r < 4; r++) acc[mt][nt][r] = 0.0f;

    float4 ra;
    auto ldA = [&](int ch) {
        ra = __ldcg((const float4*)&mperm[(ch * 16 + klocal) * BATCH + m0 + row4]);
    };
    auto stA = [&](int buf) {
        int s = klocal >> 3, qq = klocal & 3, hi = (klocal >> 2) & 1;
        uint32_t* d = sm + buf * 1024 + s * 512 + row4 * 8 + qq * 2 + hi;
        d[0] = f2tf32(ra.x); d[8] = f2tf32(ra.y);
        d[16] = f2tf32(ra.z); d[24] = f2tf32(ra.w);
    };
    auto ldW = [&](int ch, int buf) {
        const uint32_t* src = Pblk + (size_t)ch * 1024 + tid * 4;
        uint32_t dst = sb + (2048 + buf * 1024 + tid * 4) * 4;
        cp16(dst, src);
        CP_COMMIT();
    };

    ldW(0, 0);
    ldA(0);
    stA(0);
    CP_WAIT0();
    __syncthreads();

    for (int ch = 0; ch < 48; ch++) {
        int buf = ch & 1;
        bool more = (ch + 1 < 48);
        if (more) { ldW(ch + 1, buf ^ 1); ldA(ch + 1); }

        const uint32_t* bA = sm + buf * 1024;
        const uint32_t* bW = sm + 2048 + buf * 1024;
#pragma unroll
        for (int s = 0; s < 2; s++) {
            uint2 a02[2], a13[2];
#pragma unroll
            for (int mt = 0; mt < 2; mt++) {
                int r = wm * 32 + mt * 16 + grp;
                a02[mt] = *(const uint2*)&bA[s * 512 + r * 8 + q * 2];
                a13[mt] = *(const uint2*)&bA[s * 512 + (r + 8) * 8 + q * 2];
            }
#pragma unroll
            for (int nt = 0; nt < 2; nt++) {
                int col = wn * 16 + nt * 8 + grp;
                uint2 b01 = *(const uint2*)&bW[s * 512 + col * 8 + q * 2];
#pragma unroll
                for (int mt = 0; mt < 2; mt++)
                    mma_tf32(acc[mt][nt][0], acc[mt][nt][1], acc[mt][nt][2], acc[mt][nt][3],
                             a02[mt].x, a13[mt].x, a02[mt].y, a13[mt].y, b01.x, b01.y);
            }
        }
        if (more) stA(buf ^ 1);
        CP_WAIT0();
        __syncthreads();
    }

#pragma unroll
    for (int mt = 0; mt < 2; mt++)
#pragma unroll
        for (int nt = 0; nt < 2; nt++) {
            int row = m0 + wm * 32 + mt * 16 + grp;
            int col = nt4 * 64 + wn * 16 + nt * 8 + 2 * q;
            *(float2*)&hout[row * PJDIM + col] =
                make_float2(acc[mt][nt][0], acc[mt][nt][1]);
            *(float2*)&hout[(row + 8) * PJDIM + col] =
                make_float2(acc[mt][nt][2], acc[mt][nt][3]);
        }
}

// ---------------- persistent driver --------------------------------------------
__global__ void __launch_bounds__(256, 1)
lstm_persistent(const float* __restrict__ x,
                const float* __restrict__ b0, const float* __restrict__ b1,
                const float* __restrict__ b2,
                float* __restrict__ out)
{
    extern __shared__ uint32_t dynsmem[];   // sA[2][1024] + sW[2][4096] = 10240 words
    __shared__ float red[8];
    uint32_t* sm = dynsmem;
    uint32_t sb = (uint32_t)__cvta_generic_to_shared(dynsmem);

    const int bid = blockIdx.x;
    const int tid = threadIdx.x;

    for (int i = bid * 256 + tid; i < NLAYERS * HDIM * BATCH; i += NBLK * 256)
        ((float*)g_c)[i] = 0.0f;
    for (int i = bid * 256 + tid; i < NLAYERS * BATCH * PJDIM; i += NBLK * 256)
        ((float*)g_h)[i] = 0.0f;
    grid_barrier();

    const int p_layer = bid / 40;
    const int p_rem   = bid % 40;
    const int p_m0    = (p_rem % 10) * 64;
    const int p_nt4   = p_rem / 10;
    const uint32_t* Pblk = g_Ppre + ((size_t)p_layer * 4 + p_nt4) * 48 * 1024;

    for (int s = 0; s < T_STEPS + 2; s++) {
        // phase A: gates wavefront (layer l at time s-l)
        if (s < T_STEPS)
            gates_mma<FDIM, NCH0, true>(x + (size_t)s * BATCH * FDIM, g_h[0],
                                        g_W0pre, b0, g_c[0], g_m[0], sm, sb);
        if (s >= 1 && s - 1 < T_STEPS)
            gates_mma<PJDIM, NCH12, false>(g_h[0], g_h[1], g_W1pre, b1,
                                           g_c[1], g_m[1], sm, sb);
        if (s >= 2 && s - 2 < T_STEPS)
            gates_mma<PJDIM, NCH12, false>(g_h[1], g_h[2], g_W2pre, b2,
                                           g_c[2], g_m[2], sm, sb);
        grid_barrier();

        // phase B: one 64x64 proj tile per block
        if (s - p_layer >= 0 && s - p_layer < T_STEPS)
            proj_mma(g_m[p_layer], Pblk, g_h[p_layer], p_m0, p_nt4, sm, sb);
        grid_barrier();
    }

    for (int b = bid; b < BATCH; b += NBLK) {
        float v = __ldcg(&g_h[NLAYERS - 1][b * PJDIM + tid]);
        float sm2 = v * v;
#pragma unroll
        for (int o = 16; o > 0; o >>= 1) sm2 += __shfl_xor_sync(0xffffffffu, sm2, o);
        if ((tid & 31) == 0) red[tid >> 5] = sm2;
        __syncthreads();
        float tot = red[0] + red[1] + red[2] + red[3] +
                    red[4] + red[5] + red[6] + red[7];
        out[b * PJDIM + tid] = v * rsqrtf(fmaxf(tot, 1e-12f));
        __syncthreads();
    }
}

extern "C" void kernel_launch(void* const* d_in, const int* in_sizes, int n_in,
                              void* d_out, int out_size)
{
    const float* x  = (const float*)d_in[0];
    const float* W0 = (const float*)d_in[1];
    const float* b0 = (const float*)d_in[2];
    const float* P0 = (const float*)d_in[3];
    const float* W1 = (const float*)d_in[4];
    const float* b1 = (const float*)d_in[5];
    const float* P1 = (const float*)d_in[6];
    const float* W2 = (const float*)d_in[7];
    const float* b2 = (const float*)d_in[8];
    const float* P2 = (const float*)d_in[9];
    float* out = (float*)d_out;
    (void)in_sizes; (void)n_in; (void)out_size;

    // words: 12*19*4096 + 2*12*32*4096 + 3*4*48*1024 = 4,669,440 -> 18240 blocks
    precompute_weights<<<18240, 256>>>(W0, W1, W2, P0, P1, P2);
    lstm_persistent<<<NBLK, 256, 40960>>>(x, b0, b1, b2, out);
}